// round 2
// baseline (speedup 1.0000x reference)
#include <cuda_runtime.h>
#include <math.h>

// Problem constants
// B=128, T=256, W=256, D=128, C=256, K=12, Tp=244, TEMP=0.1
#define N_BT     32768      // B*T
#define TP       244
#define NROWS_L  374784     // K*B*Tp
#define LOG_SMEM ((128*68 + 128*260)*4)

// ---------------- scratch (device globals; no allocations allowed) ----------
__device__ __align__(16) float g_z   [4194304];   // [32768,128] normalized z
__device__ __align__(16) float g_c   [8388608];   // [32768,256] c_seq
__device__ __align__(16) float g_h1  [8388608];   // [32768,256] encoder hidden
__device__ __align__(16) float g_gx  [25165824];  // [32768,768] GRU input gates
__device__ __align__(16) float g_U   [50331648];  // [12,32768,128] unnormalized preds
__device__ __align__(16) float g_invn[393216];    // [12,32768] 1/(max(||u||,eps)*TEMP)
__device__ __align__(16) float g_w1T [65536];     // enc_w1^T   [256,256]
__device__ __align__(16) float g_w2T [32768];     // enc_w2^T   [128,256]
__device__ __align__(16) float g_WkT [393216];    // Wk_w^T     [12,128,256]
__device__ __align__(16) float g_WhhT[196608];    // W_hh^T     [256][768] (j-major)
__device__ __align__(16) float g_part[12288];     // per-block (loss, acc) partials

// ---------------- prep: transposes --------------------------------------
__global__ void prep_transpose(const float* __restrict__ w1, const float* __restrict__ w2,
                               const float* __restrict__ whh, const float* __restrict__ wk)
{
    long i = (long)blockIdx.x * 256 + threadIdx.x;
    if (i < 65536) {            // w1T[n][k] = w1[k][n], 256x256
        int n = (int)(i >> 8), k = (int)(i & 255);
        g_w1T[n*256 + k] = w1[k*256 + n];
    }
    if (i < 32768) {            // w2T[n][k] = w2[k][n], n<128,k<256
        int n = (int)(i >> 8), k = (int)(i & 255);
        g_w2T[n*256 + k] = w2[k*128 + n];
    }
    if (i < 196608) {           // WhhT[j][g] = whh[g][j]
        int g = (int)(i / 256), j = (int)(i % 256);
        g_WhhT[j*768 + g] = whh[g*256 + j];
    }
    if (i < 393216) {           // WkT[kk][d][c] = wk[kk][c][d]
        long kk = i / 32768; long r = i % 32768;
        int d = (int)(r >> 8), c = (int)(r & 255);
        g_WkT[kk*32768 + d*256 + c] = wk[kk*32768 + c*128 + d];
    }
}

// ---------------- generic NT GEMM: C = A @ B^T + bias (opt relu) ---------
// A row-major [M,K], B row-major [N,K], C row-major [M,N]. M%128==0, N%128==0, K%16==0.
// A and B must be 16B-aligned.
__global__ __launch_bounds__(256) void gemm_nt(
    const float* __restrict__ A, const float* __restrict__ Bm,
    const float* __restrict__ bias, float* __restrict__ Cm,
    int M, int N, int K, int relu,
    long sB, long sBias, long sC)
{
    __shared__ float As[16][132];
    __shared__ float Bs[16][132];
    const float* Bz = Bm  + (long)blockIdx.z * sB;
    const float* bz = bias + (long)blockIdx.z * sBias;
    float*       Cz = Cm  + (long)blockIdx.z * sC;

    int m0 = blockIdx.y * 128, n0 = blockIdx.x * 128;
    int tid = threadIdx.x;
    int tx = tid & 15, ty = tid >> 4;

    float acc[8][8];
    #pragma unroll
    for (int i = 0; i < 8; i++)
        #pragma unroll
        for (int j = 0; j < 8; j++) acc[i][j] = 0.f;

    const float* Ab = A  + (long)m0 * K;
    const float* Bb = Bz + (long)n0 * K;

    for (int k0 = 0; k0 < K; k0 += 16) {
        #pragma unroll
        for (int l = 0; l < 2; l++) {
            int f = tid + l*256;
            int row = f >> 2, c4 = (f & 3) << 2;
            float4 va = *(const float4*)(Ab + (long)row*K + k0 + c4);
            As[c4+0][row] = va.x; As[c4+1][row] = va.y;
            As[c4+2][row] = va.z; As[c4+3][row] = va.w;
            float4 vb = *(const float4*)(Bb + (long)row*K + k0 + c4);
            Bs[c4+0][row] = vb.x; Bs[c4+1][row] = vb.y;
            Bs[c4+2][row] = vb.z; Bs[c4+3][row] = vb.w;
        }
        __syncthreads();
        #pragma unroll
        for (int kk = 0; kk < 16; kk++) {
            float4 a0 = *(const float4*)&As[kk][ty*8];
            float4 a1 = *(const float4*)&As[kk][ty*8 + 4];
            float4 b0 = *(const float4*)&Bs[kk][tx*8];
            float4 b1 = *(const float4*)&Bs[kk][tx*8 + 4];
            float a[8] = {a0.x,a0.y,a0.z,a0.w,a1.x,a1.y,a1.z,a1.w};
            float b[8] = {b0.x,b0.y,b0.z,b0.w,b1.x,b1.y,b1.z,b1.w};
            #pragma unroll
            for (int i = 0; i < 8; i++)
                #pragma unroll
                for (int j = 0; j < 8; j++) acc[i][j] += a[i]*b[j];
        }
        __syncthreads();
    }

    float bb[8];
    #pragma unroll
    for (int j = 0; j < 8; j++) bb[j] = bz[n0 + tx*8 + j];
    #pragma unroll
    for (int i = 0; i < 8; i++) {
        float* Crow = Cz + (long)(m0 + ty*8 + i)*N + n0 + tx*8;
        #pragma unroll
        for (int j = 0; j < 8; j++) {
            float v = acc[i][j] + bb[j];
            if (relu) v = fmaxf(v, 0.f);
            Crow[j] = v;
        }
    }
}

// ---------------- row L2-normalize (dim 128), in place -------------------
__global__ void normz_kernel(float* __restrict__ z, int rows)
{
    int w = (blockIdx.x * blockDim.x + threadIdx.x) >> 5;
    int lane = threadIdx.x & 31;
    if (w >= rows) return;
    float4* p = (float4*)(z + (long)w * 128);
    float4 v = p[lane];
    float ss = v.x*v.x + v.y*v.y + v.z*v.z + v.w*v.w;
    #pragma unroll
    for (int o = 16; o; o >>= 1) ss += __shfl_xor_sync(0xffffffffu, ss, o);
    float inv = 1.f / fmaxf(sqrtf(ss), 1e-12f);
    v.x *= inv; v.y *= inv; v.z *= inv; v.w *= inv;
    p[lane] = v;
}

// ---------------- inv-norm (and fold 1/TEMP) for U rows ------------------
__global__ void invn_kernel()
{
    int w = (blockIdx.x * blockDim.x + threadIdx.x) >> 5;
    int lane = threadIdx.x & 31;
    if (w >= 12*32768) return;
    const float4* p = (const float4*)(g_U + (long)w * 128);
    float4 v = p[lane];
    float ss = v.x*v.x + v.y*v.y + v.z*v.z + v.w*v.w;
    #pragma unroll
    for (int o = 16; o; o >>= 1) ss += __shfl_xor_sync(0xffffffffu, ss, o);
    if (lane == 0)
        g_invn[w] = 1.f / (fmaxf(sqrtf(ss), 1e-12f) * 0.1f);
}

// ---------------- GRU: one persistent block per batch element ------------
__global__ __launch_bounds__(256) void gru_kernel(const float* __restrict__ bhh)
{
    __shared__ __align__(16) float sh_h[256];
    __shared__ __align__(16) float sh_gh[768];
    __shared__ __align__(16) float sh_gx[768];
    __shared__ float sh_bhh[768];
    int b = blockIdx.x, tid = threadIdx.x;

    sh_h[tid] = 0.f;
    for (int i = tid; i < 768; i += 256) sh_bhh[i] = bhh[i];
    __syncthreads();

    const float4* Wt4 = (const float4*)g_WhhT;   // [j][192 float4]
    const float*  gxb = g_gx + (long)b * 256 * 768;
    float*        cb  = g_c  + (long)b * 256 * 256;

    for (int t = 0; t < 256; t++) {
        if (tid < 192) {
            // gh[4*tid .. 4*tid+3] = sum_j W_hh[g][j] * h[j]
            float4 acc = make_float4(0.f, 0.f, 0.f, 0.f);
            const float4* Wp = Wt4 + tid;
            #pragma unroll 2
            for (int j4 = 0; j4 < 64; j4++) {
                float4 h4 = *(const float4*)(sh_h + 4*j4);
                float4 w0 = Wp[(4*j4+0)*192];
                float4 w1 = Wp[(4*j4+1)*192];
                float4 w2 = Wp[(4*j4+2)*192];
                float4 w3 = Wp[(4*j4+3)*192];
                acc.x += w0.x*h4.x + w1.x*h4.y + w2.x*h4.z + w3.x*h4.w;
                acc.y += w0.y*h4.x + w1.y*h4.y + w2.y*h4.z + w3.y*h4.w;
                acc.z += w0.z*h4.x + w1.z*h4.y + w2.z*h4.z + w3.z*h4.w;
                acc.w += w0.w*h4.x + w1.w*h4.y + w2.w*h4.z + w3.w*h4.w;
            }
            *(float4*)(sh_gh + 4*tid) = acc;
        } else {
            int i0 = tid - 192;
            const float4* gx4 = (const float4*)(gxb + (long)t * 768);
            float4* dst = (float4*)sh_gx;
            #pragma unroll
            for (int l = 0; l < 3; l++) dst[i0 + l*64] = gx4[i0 + l*64];
        }
        __syncthreads();
        {
            int c = tid;
            float xr = sh_gx[c], xz = sh_gx[256+c], xn = sh_gx[512+c];
            float hr = sh_gh[c]     + sh_bhh[c];
            float hz = sh_gh[256+c] + sh_bhh[256+c];
            float hn = sh_gh[512+c] + sh_bhh[512+c];
            float r  = 1.f / (1.f + expf(-(xr + hr)));
            float zg = 1.f / (1.f + expf(-(xz + hz)));
            float n  = tanhf(xn + r*hn);
            float h  = sh_h[c];
            float hn2 = (1.f - zg)*n + zg*h;
            sh_h[c] = hn2;
            cb[t*256 + c] = hn2;
        }
        __syncthreads();
    }
}

// ---------------- fused logits + logsumexp/pos/negmax reduction ----------
// grid (4 t-tiles, 128 b, 12 k); block 256; all 256 s handled per block.
#define ZSTR 260
#define USTR 68
__global__ __launch_bounds__(256) void logits_kernel()
{
    extern __shared__ float sm[];
    float* Ut = sm;                  // [d][row] stride USTR
    float* Zt = sm + 128*USTR;       // [d][s]   stride ZSTR
    int tile = blockIdx.x, b = blockIdx.y, k = blockIdx.z;
    int tid = threadIdx.x;
    int tx = tid & 31, ty = tid >> 5;

    const float* Zb = g_z + (long)b * 256 * 128;
    #pragma unroll
    for (int l = 0; l < 32; l++) {
        int f = tid + l*256;
        int s = f >> 5, d4 = (f & 31) << 2;
        float4 v = *(const float4*)(Zb + s*128 + d4);
        Zt[(d4+0)*ZSTR + s] = v.x; Zt[(d4+1)*ZSTR + s] = v.y;
        Zt[(d4+2)*ZSTR + s] = v.z; Zt[(d4+3)*ZSTR + s] = v.w;
    }
    int t0 = tile * 64;
    const float* Ub = g_U + ((long)k*32768 + (long)b*256 + t0) * 128;
    #pragma unroll
    for (int l = 0; l < 8; l++) {
        int f = tid + l*256;
        int r = f >> 5, d4 = (f & 31) << 2;
        float4 v = *(const float4*)(Ub + r*128 + d4);
        Ut[(d4+0)*USTR + r] = v.x; Ut[(d4+1)*USTR + r] = v.y;
        Ut[(d4+2)*USTR + r] = v.z; Ut[(d4+3)*USTR + r] = v.w;
    }
    __syncthreads();

    float acc[8][8];
    #pragma unroll
    for (int i = 0; i < 8; i++)
        #pragma unroll
        for (int j = 0; j < 8; j++) acc[i][j] = 0.f;

    for (int d = 0; d < 128; d++) {
        float4 a0 = *(const float4*)&Ut[d*USTR + ty*8];
        float4 a1 = *(const float4*)&Ut[d*USTR + ty*8 + 4];
        float4 b0 = *(const float4*)&Zt[d*ZSTR + tx*8];
        float4 b1 = *(const float4*)&Zt[d*ZSTR + tx*8 + 4];
        float a[8] = {a0.x,a0.y,a0.z,a0.w,a1.x,a1.y,a1.z,a1.w};
        float bv[8] = {b0.x,b0.y,b0.z,b0.w,b1.x,b1.y,b1.z,b1.w};
        #pragma unroll
        for (int i = 0; i < 8; i++)
            #pragma unroll
            for (int j = 0; j < 8; j++) acc[i][j] += a[i]*bv[j];
    }

    const float* invb = g_invn + (long)k*32768 + (long)b*256;
    float loss_tot = 0.f, acc_tot = 0.f;
    #pragma unroll
    for (int i = 0; i < 8; i++) {
        int t = t0 + ty*8 + i;           // uniform across warp
        bool valid = (t < TP);
        float inv = valid ? invb[t] : 0.f;
        int spos = t + k + 1;
        float lsum = 0.f, nmax = -3.0e38f, pos = -3.0e38f;
        #pragma unroll
        for (int j = 0; j < 8; j++) {
            int s = tx*8 + j;
            float l = acc[i][j] * inv;
            lsum += expf(l);
            if (s == spos) pos = l;
            else           nmax = fmaxf(nmax, l);
        }
        #pragma unroll
        for (int o = 16; o; o >>= 1) {
            lsum += __shfl_xor_sync(0xffffffffu, lsum, o);
            nmax = fmaxf(nmax, __shfl_xor_sync(0xffffffffu, nmax, o));
            pos  = fmaxf(pos,  __shfl_xor_sync(0xffffffffu, pos,  o));
        }
        if (valid && tx == 0) {
            loss_tot += logf(lsum) - pos;
            acc_tot  += (pos >= nmax) ? 1.f : 0.f;
        }
    }
    __shared__ float wl[8], wa[8];
    if (tx == 0) { wl[ty] = loss_tot; wa[ty] = acc_tot; }
    __syncthreads();
    if (tid == 0) {
        float L = 0.f, A = 0.f;
        #pragma unroll
        for (int w = 0; w < 8; w++) { L += wl[w]; A += wa[w]; }
        long bid = ((long)k*128 + b)*4 + tile;
        g_part[bid*2]   = L;
        g_part[bid*2+1] = A;
    }
}

// ---------------- final deterministic reduction --------------------------
__global__ void final_kernel(float* __restrict__ out)
{
    __shared__ float sl[256], sa[256];
    int tid = threadIdx.x;
    float L = 0.f, A = 0.f;
    for (int i = tid; i < 6144; i += 256) { L += g_part[i*2]; A += g_part[i*2+1]; }
    sl[tid] = L; sa[tid] = A;
    __syncthreads();
    for (int o = 128; o; o >>= 1) {
        if (tid < o) { sl[tid] += sl[tid+o]; sa[tid] += sa[tid+o]; }
        __syncthreads();
    }
    if (tid == 0) {
        out[0] = sl[0] / (float)NROWS_L;
        out[1] = sa[0] / (float)NROWS_L * 100.f;
    }
}

// ---------------- copy z and c into d_out (8B-aligned dst => float2) -----
__global__ void copyout_kernel(float* __restrict__ out)
{
    long i = (long)blockIdx.x * 256 + threadIdx.x;   // float2 index
    float2* dst = (float2*)(out + 2);                // 8B aligned
    const long NZ2 = 2097152;                        // 4194304/2
    const long NC2 = 4194304;                        // 8388608/2
    if (i < NZ2) {
        dst[i] = ((const float2*)g_z)[i];
    } else if (i < NZ2 + NC2) {
        dst[i] = ((const float2*)g_c)[i - NZ2];
    }
}

// ---------------- host launcher ------------------------------------------
extern "C" void kernel_launch(void* const* d_in, const int* in_sizes, int n_in,
                              void* d_out, int out_size)
{
    const float* rr  = (const float*)d_in[0];
    const float* w1  = (const float*)d_in[1];
    const float* b1  = (const float*)d_in[2];
    const float* w2  = (const float*)d_in[3];
    const float* b2  = (const float*)d_in[4];
    const float* Wih = (const float*)d_in[5];
    const float* Whh = (const float*)d_in[6];
    const float* bih = (const float*)d_in[7];
    const float* bhh = (const float*)d_in[8];
    const float* Wkw = (const float*)d_in[9];
    const float* Wkb = (const float*)d_in[10];

    float* out = (float*)d_out;

    float *pz, *pc, *ph1, *pgx, *pU, *pw1T, *pw2T, *pWkT;
    cudaGetSymbolAddress((void**)&pz,   g_z);
    cudaGetSymbolAddress((void**)&pc,   g_c);
    cudaGetSymbolAddress((void**)&ph1,  g_h1);
    cudaGetSymbolAddress((void**)&pgx,  g_gx);
    cudaGetSymbolAddress((void**)&pU,   g_U);
    cudaGetSymbolAddress((void**)&pw1T, g_w1T);
    cudaGetSymbolAddress((void**)&pw2T, g_w2T);
    cudaGetSymbolAddress((void**)&pWkT, g_WkT);

    // 0. weight transposes
    prep_transpose<<<1536, 256>>>(w1, w2, Whh, Wkw);
    // 1. encoder layer 1 (relu)
    gemm_nt<<<dim3(2, 256, 1), 256>>>(rr, pw1T, b1, ph1, N_BT, 256, 256, 1, 0, 0, 0);
    // 2. encoder layer 2 -> z (unnormalized), then normalize in place
    gemm_nt<<<dim3(1, 256, 1), 256>>>(ph1, pw2T, b2, pz, N_BT, 128, 256, 0, 0, 0, 0);
    normz_kernel<<<N_BT/8, 256>>>(pz, N_BT);
    // 3. gx = z @ W_ih^T + b_ih
    gemm_nt<<<dim3(6, 256, 1), 256>>>(pz, Wih, bih, pgx, N_BT, 768, 128, 0, 0, 0, 0);
    // 4. GRU scan -> c_seq (g_c)
    gru_kernel<<<128, 256>>>(bhh);
    // 5. U[k] = c_seq @ Wk_w[k] + Wk_b[k]   (batched over k via grid.z)
    gemm_nt<<<dim3(1, 256, 12), 256>>>(pc, pWkT, Wkb, pU, N_BT, 128, 256, 0,
                                       32768L, 128L, (long)N_BT * 128);
    // 6. inverse norms (folding 1/TEMP)
    invn_kernel<<<(12*N_BT)/8, 256>>>();
    // 7. fused logits + reductions
    cudaFuncSetAttribute(logits_kernel, cudaFuncAttributeMaxDynamicSharedMemorySize, LOG_SMEM);
    logits_kernel<<<dim3(4, 128, 12), 256, LOG_SMEM>>>();
    // 8. final loss/accuracy
    final_kernel<<<1, 256>>>(out);
    // 9. copy z_seq and c_seq into d_out
    copyout_kernel<<<24576, 256>>>(out);
}

// round 3
// speedup vs baseline: 1.4389x; 1.4389x over previous
#include <cuda_runtime.h>
#include <math.h>
#include <stdint.h>

// B=128, T=256, W=256, D=128, C=256, K=12, Tp=244, TEMP=0.1
#define N_BT     32768
#define TP       244
#define NROWS_L  374784
#define LOG_SMEM ((128*68 + 128*260)*4)
// GRU smem: W 96*260 + h 2*2048 + gh 96*9 + gx 2*800 + bh 96 floats
#define GRU_SMEM ((96*260 + 4096 + 864 + 1600 + 96)*4)

// ---------------- packed f32x2 helpers ----------------------------------
#define FMA2(d,a,b) asm("fma.rn.f32x2 %0, %1, %2, %0;" : "+l"(d) : "l"(a), "l"(b))
__device__ __forceinline__ unsigned long long pack2(float x) {
    unsigned long long r; asm("mov.b64 %0, {%1, %1};" : "=l"(r) : "f"(x)); return r;
}
__device__ __forceinline__ void unpack2(unsigned long long v, float& lo, float& hi) {
    asm("mov.b64 {%0, %1}, %2;" : "=f"(lo), "=f"(hi) : "l"(v));
}
__device__ __forceinline__ float pairsum(unsigned long long v) {
    float a, b; unpack2(v, a, b); return a + b;
}
__device__ __forceinline__ uint32_t s2u(const void* p) {
    uint32_t a; asm("{ .reg .u64 t; cvta.to.shared.u64 t, %1; cvt.u32.u64 %0, t; }" : "=r"(a) : "l"(p));
    return a;
}
__device__ __forceinline__ uint32_t mapa_u32(uint32_t addr, uint32_t rank) {
    uint32_t r; asm("mapa.shared::cluster.u32 %0, %1, %2;" : "=r"(r) : "r"(addr), "r"(rank));
    return r;
}
__device__ __forceinline__ void st_cluster_f32(uint32_t addr, float v) {
    asm volatile("st.shared::cluster.f32 [%0], %1;" :: "r"(addr), "f"(v) : "memory");
}

// ---------------- scratch ------------------------------------------------
__device__ __align__(16) float g_z   [4194304];   // [32768,128] normalized z
__device__ __align__(16) float g_c   [8388608];   // [32768,256] c_seq
__device__ __align__(16) float g_h1  [8388608];   // [32768,256]
__device__ __align__(16) float g_gx  [25165824];  // [32768,768]
__device__ __align__(16) float g_U   [50331648];  // [12,32768,128] row-scaled preds*10
__device__ __align__(16) float g_w1T [65536];
__device__ __align__(16) float g_w2T [32768];
__device__ __align__(16) float g_WkT [393216];
__device__ __align__(16) float g_part[12288];

// ---------------- prep: transposes --------------------------------------
__global__ void prep_transpose(const float* __restrict__ w1, const float* __restrict__ w2,
                               const float* __restrict__ wk)
{
    long i = (long)blockIdx.x * 256 + threadIdx.x;
    if (i < 65536) {
        int n = (int)(i >> 8), k = (int)(i & 255);
        g_w1T[n*256 + k] = w1[k*256 + n];
    }
    if (i < 32768) {
        int n = (int)(i >> 8), k = (int)(i & 255);
        g_w2T[n*256 + k] = w2[k*128 + n];
    }
    if (i < 393216) {
        long kk = i / 32768; long r = i % 32768;
        int d = (int)(r >> 8), c = (int)(r & 255);
        g_WkT[kk*32768 + d*256 + c] = wk[kk*32768 + c*128 + d];
    }
}

// ---------------- NT GEMM, f32x2, double-buffered ------------------------
// C = A @ B^T + bias. mode: 0 plain(+relu opt), 1 scale rows by 10/max(||r||,eps),
// 2 normalize rows (1/max(||r||,eps)). modes 1/2 require N==128 (gridDim.x==1).
__global__ __launch_bounds__(256) void gemm_nt(
    const float* __restrict__ A, const float* __restrict__ Bm,
    const float* __restrict__ bias, float* __restrict__ Cm,
    int M, int N, int K, int relu, int mode,
    long sB, long sBias, long sC)
{
    __shared__ float As[2][16][132];
    __shared__ float Bs[2][16][132];
    __shared__ float rs[128][17];
    __shared__ float rinv[128];

    const float* Bz = Bm  + (long)blockIdx.z * sB;
    const float* bz = bias + (long)blockIdx.z * sBias;
    float*       Cz = Cm  + (long)blockIdx.z * sC;

    int m0 = blockIdx.y * 128, n0 = blockIdx.x * 128;
    int tid = threadIdx.x;
    int tx = tid & 15, ty = tid >> 4;

    const float* Ab = A  + (long)m0 * K;
    const float* Bb = Bz + (long)n0 * K;
    int lrow = tid >> 2, lc4 = (tid & 3) << 2;

    unsigned long long acc2[8][4];
    #pragma unroll
    for (int i = 0; i < 8; i++)
        #pragma unroll
        for (int j = 0; j < 4; j++) acc2[i][j] = 0ULL;

    float4 ra0, ra1, rb0, rb1;
    // prologue: tile 0
    ra0 = *(const float4*)(Ab + (long)lrow*K + lc4);
    ra1 = *(const float4*)(Ab + (long)(lrow+64)*K + lc4);
    rb0 = *(const float4*)(Bb + (long)lrow*K + lc4);
    rb1 = *(const float4*)(Bb + (long)(lrow+64)*K + lc4);
    {
        As[0][lc4+0][lrow] = ra0.x; As[0][lc4+1][lrow] = ra0.y;
        As[0][lc4+2][lrow] = ra0.z; As[0][lc4+3][lrow] = ra0.w;
        As[0][lc4+0][lrow+64] = ra1.x; As[0][lc4+1][lrow+64] = ra1.y;
        As[0][lc4+2][lrow+64] = ra1.z; As[0][lc4+3][lrow+64] = ra1.w;
        Bs[0][lc4+0][lrow] = rb0.x; Bs[0][lc4+1][lrow] = rb0.y;
        Bs[0][lc4+2][lrow] = rb0.z; Bs[0][lc4+3][lrow] = rb0.w;
        Bs[0][lc4+0][lrow+64] = rb1.x; Bs[0][lc4+1][lrow+64] = rb1.y;
        Bs[0][lc4+2][lrow+64] = rb1.z; Bs[0][lc4+3][lrow+64] = rb1.w;
    }
    __syncthreads();

    int NT = K >> 4;
    for (int t = 0; t < NT; t++) {
        int cur = t & 1;
        bool nxt = (t + 1 < NT);
        if (nxt) {
            int k0 = (t+1) << 4;
            ra0 = *(const float4*)(Ab + (long)lrow*K + k0 + lc4);
            ra1 = *(const float4*)(Ab + (long)(lrow+64)*K + k0 + lc4);
            rb0 = *(const float4*)(Bb + (long)lrow*K + k0 + lc4);
            rb1 = *(const float4*)(Bb + (long)(lrow+64)*K + k0 + lc4);
        }
        #pragma unroll
        for (int kk = 0; kk < 16; kk++) {
            float4 a0 = *(const float4*)&As[cur][kk][ty*8];
            float4 a1 = *(const float4*)&As[cur][kk][ty*8 + 4];
            ulonglong2 b01 = *(const ulonglong2*)&Bs[cur][kk][tx*8];
            ulonglong2 b23 = *(const ulonglong2*)&Bs[cur][kk][tx*8 + 4];
            float a[8] = {a0.x,a0.y,a0.z,a0.w,a1.x,a1.y,a1.z,a1.w};
            #pragma unroll
            for (int i = 0; i < 8; i++) {
                unsigned long long av = pack2(a[i]);
                FMA2(acc2[i][0], av, b01.x);
                FMA2(acc2[i][1], av, b01.y);
                FMA2(acc2[i][2], av, b23.x);
                FMA2(acc2[i][3], av, b23.y);
            }
        }
        if (nxt) {
            int nb = cur ^ 1;
            As[nb][lc4+0][lrow] = ra0.x; As[nb][lc4+1][lrow] = ra0.y;
            As[nb][lc4+2][lrow] = ra0.z; As[nb][lc4+3][lrow] = ra0.w;
            As[nb][lc4+0][lrow+64] = ra1.x; As[nb][lc4+1][lrow+64] = ra1.y;
            As[nb][lc4+2][lrow+64] = ra1.z; As[nb][lc4+3][lrow+64] = ra1.w;
            Bs[nb][lc4+0][lrow] = rb0.x; Bs[nb][lc4+1][lrow] = rb0.y;
            Bs[nb][lc4+2][lrow] = rb0.z; Bs[nb][lc4+3][lrow] = rb0.w;
            Bs[nb][lc4+0][lrow+64] = rb1.x; Bs[nb][lc4+1][lrow+64] = rb1.y;
            Bs[nb][lc4+2][lrow+64] = rb1.z; Bs[nb][lc4+3][lrow+64] = rb1.w;
            __syncthreads();
        }
    }

    // epilogue
    float v[8][8];
    float bb[8];
    #pragma unroll
    for (int j = 0; j < 8; j++) bb[j] = bz[n0 + tx*8 + j];
    #pragma unroll
    for (int i = 0; i < 8; i++)
        #pragma unroll
        for (int jp = 0; jp < 4; jp++) {
            float lo, hi; unpack2(acc2[i][jp], lo, hi);
            v[i][2*jp]   = lo + bb[2*jp];
            v[i][2*jp+1] = hi + bb[2*jp+1];
        }

    if (mode) {
        #pragma unroll
        for (int i = 0; i < 8; i++) {
            float ss = 0.f;
            #pragma unroll
            for (int j = 0; j < 8; j++) ss += v[i][j]*v[i][j];
            rs[ty*8+i][tx] = ss;
        }
        __syncthreads();
        if (tid < 128) {
            float ss = 0.f;
            #pragma unroll
            for (int x = 0; x < 16; x++) ss += rs[tid][x];
            float inv = 1.f / fmaxf(sqrtf(ss), 1e-12f);
            if (mode == 1) inv *= 10.f;
            rinv[tid] = inv;
        }
        __syncthreads();
        #pragma unroll
        for (int i = 0; i < 8; i++) {
            float sc = rinv[ty*8+i];
            #pragma unroll
            for (int j = 0; j < 8; j++) v[i][j] *= sc;
        }
    }

    #pragma unroll
    for (int i = 0; i < 8; i++) {
        float* Crow = Cz + (long)(m0 + ty*8 + i)*N + n0 + tx*8;
        #pragma unroll
        for (int j = 0; j < 8; j++) {
            float x = v[i][j];
            if (relu) x = fmaxf(x, 0.f);
            Crow[j] = x;
        }
    }
}

// ---------------- GRU: weight-stationary 8-CTA clusters ------------------
// 16 clusters x 8 CTAs. CTA rank r owns channels [32r,32r+32) (96 W_hh rows
// in SMEM) for its cluster's 8 batches. h replicated per CTA, pushed via
// DSMEM each step, one cluster barrier per step.
__global__ __launch_bounds__(256, 1) __cluster_dims__(8, 1, 1)
void gru_cluster(const float* __restrict__ Whh, const float* __restrict__ bhh)
{
    extern __shared__ float s[];
    float* W_s  = s;                       // [96][260]
    float* hb   = s + 96*260;              // [2][8][256]
    float* gh_s = hb + 4096;               // [96][9]
    float* gx_s = gh_s + 864;              // [2][8][100]
    float* bh_s = gx_s + 1600;             // [96]

    int tid  = threadIdx.x;
    int rank = blockIdx.x & 7;
    int cl   = blockIdx.x >> 3;
    int co   = rank * 32;
    int b0   = cl * 8;

    // load 96 W_hh rows (global rows: {co+c, 256+co+c, 512+co+c})
    for (int i = tid; i < 96*256; i += 256) {
        int r = i >> 8, k = i & 255;
        int grow = (r >> 5)*256 + co + (r & 31);
        W_s[r*260 + k] = Whh[grow*256 + k];
    }
    if (tid < 96) {
        int grow = (tid >> 5)*256 + co + (tid & 31);
        bh_s[tid] = bhh[grow];
    }
    for (int i = tid; i < 2048; i += 256) hb[i] = 0.f;   // hbuf[0] = 0

    // peel: prefetch gx for t=0 into gx_s buf 0
    if (tid >= 192) {
        int f = tid - 192;
        for (int i = f; i < 768; i += 64) {
            int b = i / 96, pos = i - b*96;
            gx_s[b*100 + pos] =
                g_gx[((long)(b0+b)*256 + 0)*768 + (pos>>5)*256 + co + (pos&31)];
        }
    }

    // update-phase ids + push addresses
    int ub = tid >> 5, uc = tid & 31;
    uint32_t local_addr = s2u(hb) + (uint32_t)((ub*256 + co + uc) * 4);
    uint32_t radr[8];
    #pragma unroll
    for (int r = 0; r < 8; r++) radr[r] = mapa_u32(local_addr, r);
    float h_old = 0.f;
    float* cptr = g_c + ((long)(b0+ub)*256)*256 + co + uc;

    int g = tid >> 1, bbase = (tid & 1) * 4;
    __syncthreads();

    for (int t = 0; t < 256; t++) {
        int p = t & 1, pn = p ^ 1;
        const float* hcur = hb + p*2048;

        if (tid < 192) {
            const float* wr = W_s + g*260;
            const float* h0 = hcur + (bbase+0)*256;
            const float* h1 = hcur + (bbase+1)*256;
            const float* h2 = hcur + (bbase+2)*256;
            const float* h3 = hcur + (bbase+3)*256;
            unsigned long long a0=0ULL, a1=0ULL, a2=0ULL, a3=0ULL;
            #pragma unroll 4
            for (int k = 0; k < 64; k++) {
                ulonglong2 w = *(const ulonglong2*)(wr + k*4);
                ulonglong2 x;
                x = *(const ulonglong2*)(h0 + k*4); FMA2(a0, w.x, x.x); FMA2(a0, w.y, x.y);
                x = *(const ulonglong2*)(h1 + k*4); FMA2(a1, w.x, x.x); FMA2(a1, w.y, x.y);
                x = *(const ulonglong2*)(h2 + k*4); FMA2(a2, w.x, x.x); FMA2(a2, w.y, x.y);
                x = *(const ulonglong2*)(h3 + k*4); FMA2(a3, w.x, x.x); FMA2(a3, w.y, x.y);
            }
            gh_s[g*9 + bbase+0] = pairsum(a0);
            gh_s[g*9 + bbase+1] = pairsum(a1);
            gh_s[g*9 + bbase+2] = pairsum(a2);
            gh_s[g*9 + bbase+3] = pairsum(a3);
        } else if (t < 255) {
            int f = tid - 192;
            float* dst = gx_s + pn*800;
            for (int i = f; i < 768; i += 64) {
                int b = i / 96, pos = i - b*96;
                dst[b*100 + pos] =
                    g_gx[((long)(b0+b)*256 + (t+1))*768 + (pos>>5)*256 + co + (pos&31)];
            }
        }
        __syncthreads();

        {
            const float* gxb = gx_s + p*800 + ub*100;
            float xr = gxb[uc], xz = gxb[32+uc], xn = gxb[64+uc];
            float hr = gh_s[uc*9 + ub]        + bh_s[uc];
            float hz = gh_s[(32+uc)*9 + ub]   + bh_s[32+uc];
            float hn = gh_s[(64+uc)*9 + ub]   + bh_s[64+uc];
            float rg = 1.f / (1.f + expf(-(xr + hr)));
            float zg = 1.f / (1.f + expf(-(xz + hz)));
            float ng = tanhf(xn + rg*hn);
            float hnew = (1.f - zg)*ng + zg*h_old;
            h_old = hnew;
            uint32_t off = (uint32_t)(pn * 8192);
            #pragma unroll
            for (int r = 0; r < 8; r++) st_cluster_f32(radr[r] + off, hnew);
            cptr[t*256] = hnew;
        }
        asm volatile("barrier.cluster.arrive.aligned;" ::: "memory");
        asm volatile("barrier.cluster.wait.aligned;"   ::: "memory");
    }
}

// ---------------- fused logits + reductions ------------------------------
#define ZSTR 260
#define USTR 68
__global__ __launch_bounds__(256) void logits_kernel()
{
    extern __shared__ float sm[];
    float* Ut = sm;                  // [d][row] stride USTR
    float* Zt = sm + 128*USTR;       // [d][s]   stride ZSTR
    int tile = blockIdx.x, b = blockIdx.y, k = blockIdx.z;
    int tid = threadIdx.x;
    int tx = tid & 31, ty = tid >> 5;

    const float* Zb = g_z + (long)b * 256 * 128;
    #pragma unroll
    for (int l = 0; l < 32; l++) {
        int f = tid + l*256;
        int ss = f >> 5, d4 = (f & 31) << 2;
        float4 v = *(const float4*)(Zb + ss*128 + d4);
        Zt[(d4+0)*ZSTR + ss] = v.x; Zt[(d4+1)*ZSTR + ss] = v.y;
        Zt[(d4+2)*ZSTR + ss] = v.z; Zt[(d4+3)*ZSTR + ss] = v.w;
    }
    int t0 = tile * 64;
    const float* Ub = g_U + ((long)k*32768 + (long)b*256 + t0) * 128;
    #pragma unroll
    for (int l = 0; l < 8; l++) {
        int f = tid + l*256;
        int r = f >> 5, d4 = (f & 31) << 2;
        float4 v = *(const float4*)(Ub + r*128 + d4);
        Ut[(d4+0)*USTR + r] = v.x; Ut[(d4+1)*USTR + r] = v.y;
        Ut[(d4+2)*USTR + r] = v.z; Ut[(d4+3)*USTR + r] = v.w;
    }
    __syncthreads();

    unsigned long long acc2[8][4];
    #pragma unroll
    for (int i = 0; i < 8; i++)
        #pragma unroll
        for (int j = 0; j < 4; j++) acc2[i][j] = 0ULL;

    for (int d = 0; d < 128; d++) {
        float4 u0 = *(const float4*)&Ut[d*USTR + ty*8];
        float4 u1 = *(const float4*)&Ut[d*USTR + ty*8 + 4];
        ulonglong2 z01 = *(const ulonglong2*)&Zt[d*ZSTR + tx*8];
        ulonglong2 z23 = *(const ulonglong2*)&Zt[d*ZSTR + tx*8 + 4];
        float ua[8] = {u0.x,u0.y,u0.z,u0.w,u1.x,u1.y,u1.z,u1.w};
        #pragma unroll
        for (int i = 0; i < 8; i++) {
            unsigned long long av = pack2(ua[i]);
            FMA2(acc2[i][0], av, z01.x);
            FMA2(acc2[i][1], av, z01.y);
            FMA2(acc2[i][2], av, z23.x);
            FMA2(acc2[i][3], av, z23.y);
        }
    }

    float loss_tot = 0.f, acc_tot = 0.f;
    #pragma unroll
    for (int i = 0; i < 8; i++) {
        int t = t0 + ty*8 + i;
        bool valid = (t < TP);
        int spos = t + k + 1;
        float lrow[8];
        #pragma unroll
        for (int jp = 0; jp < 4; jp++) unpack2(acc2[i][jp], lrow[2*jp], lrow[2*jp+1]);
        float lsum = 0.f, nmax = -3.0e38f, pos = -3.0e38f;
        #pragma unroll
        for (int j = 0; j < 8; j++) {
            int sidx = tx*8 + j;
            float l = lrow[j];
            lsum += expf(l);
            if (sidx == spos) pos = l;
            else              nmax = fmaxf(nmax, l);
        }
        #pragma unroll
        for (int o = 16; o; o >>= 1) {
            lsum += __shfl_xor_sync(0xffffffffu, lsum, o);
            nmax = fmaxf(nmax, __shfl_xor_sync(0xffffffffu, nmax, o));
            pos  = fmaxf(pos,  __shfl_xor_sync(0xffffffffu, pos,  o));
        }
        if (valid && tx == 0) {
            loss_tot += logf(lsum) - pos;
            acc_tot  += (pos >= nmax) ? 1.f : 0.f;
        }
    }
    __shared__ float wl[8], wa[8];
    if (tx == 0) { wl[ty] = loss_tot; wa[ty] = acc_tot; }
    __syncthreads();
    if (tid == 0) {
        float L = 0.f, A = 0.f;
        #pragma unroll
        for (int w = 0; w < 8; w++) { L += wl[w]; A += wa[w]; }
        long bid = ((long)k*128 + b)*4 + tile;
        g_part[bid*2]   = L;
        g_part[bid*2+1] = A;
    }
}

// ---------------- final reduction ---------------------------------------
__global__ void final_kernel(float* __restrict__ out)
{
    __shared__ float sl[256], sa[256];
    int tid = threadIdx.x;
    float L = 0.f, A = 0.f;
    for (int i = tid; i < 6144; i += 256) { L += g_part[i*2]; A += g_part[i*2+1]; }
    sl[tid] = L; sa[tid] = A;
    __syncthreads();
    for (int o = 128; o; o >>= 1) {
        if (tid < o) { sl[tid] += sl[tid+o]; sa[tid] += sa[tid+o]; }
        __syncthreads();
    }
    if (tid == 0) {
        out[0] = sl[0] / (float)NROWS_L;
        out[1] = sa[0] / (float)NROWS_L * 100.f;
    }
}

// ---------------- copy z and c into d_out (8B-aligned dst) ---------------
__global__ void copyout_kernel(float* __restrict__ out)
{
    long i = (long)blockIdx.x * 256 + threadIdx.x;
    float2* dst = (float2*)(out + 2);
    const long NZ2 = 2097152;
    const long NC2 = 4194304;
    if (i < NZ2) {
        dst[i] = ((const float2*)g_z)[i];
    } else if (i < NZ2 + NC2) {
        dst[i] = ((const float2*)g_c)[i - NZ2];
    }
}

// ---------------- host launcher ------------------------------------------
extern "C" void kernel_launch(void* const* d_in, const int* in_sizes, int n_in,
                              void* d_out, int out_size)
{
    const float* rr  = (const float*)d_in[0];
    const float* w1  = (const float*)d_in[1];
    const float* b1  = (const float*)d_in[2];
    const float* w2  = (const float*)d_in[3];
    const float* b2  = (const float*)d_in[4];
    const float* Wih = (const float*)d_in[5];
    const float* Whh = (const float*)d_in[6];
    const float* bih = (const float*)d_in[7];
    const float* bhh = (const float*)d_in[8];
    const float* Wkw = (const float*)d_in[9];
    const float* Wkb = (const float*)d_in[10];

    float* out = (float*)d_out;

    float *pz, *pc, *ph1, *pgx, *pU, *pw1T, *pw2T, *pWkT;
    cudaGetSymbolAddress((void**)&pz,   g_z);
    cudaGetSymbolAddress((void**)&pc,   g_c);
    cudaGetSymbolAddress((void**)&ph1,  g_h1);
    cudaGetSymbolAddress((void**)&pgx,  g_gx);
    cudaGetSymbolAddress((void**)&pU,   g_U);
    cudaGetSymbolAddress((void**)&pw1T, g_w1T);
    cudaGetSymbolAddress((void**)&pw2T, g_w2T);
    cudaGetSymbolAddress((void**)&pWkT, g_WkT);

    static int inited = 0;
    if (!inited) {
        cudaFuncSetAttribute(logits_kernel, cudaFuncAttributeMaxDynamicSharedMemorySize, LOG_SMEM);
        cudaFuncSetAttribute(gru_cluster,   cudaFuncAttributeMaxDynamicSharedMemorySize, GRU_SMEM);
        inited = 1;
    }

    // 0. weight transposes
    prep_transpose<<<1536, 256>>>(w1, w2, Wkw);
    // 1. encoder layer 1 (relu)
    gemm_nt<<<dim3(2, 256, 1), 256>>>(rr, pw1T, b1, ph1, N_BT, 256, 256, 1, 0, 0, 0, 0);
    // 2. encoder layer 2 -> normalized z (mode 2 epilogue)
    gemm_nt<<<dim3(1, 256, 1), 256>>>(ph1, pw2T, b2, pz, N_BT, 128, 256, 0, 2, 0, 0, 0);
    // 3. gx = z @ W_ih^T + b_ih
    gemm_nt<<<dim3(6, 256, 1), 256>>>(pz, Wih, bih, pgx, N_BT, 768, 128, 0, 0, 0, 0, 0);
    // 4. GRU (clustered, weight-stationary)
    gru_cluster<<<128, 256, GRU_SMEM>>>(Whh, bhh);
    // 5. U[k] = rowscale10(c @ Wk_w[k] + Wk_b[k])  (mode 1 epilogue)
    gemm_nt<<<dim3(1, 256, 12), 256>>>(pc, pWkT, Wkb, pU, N_BT, 128, 256, 0, 1,
                                       32768L, 128L, (long)N_BT * 128);
    // 6. fused logits + reductions
    logits_kernel<<<dim3(4, 128, 12), 256, LOG_SMEM>>>();
    // 7. final loss/accuracy
    final_kernel<<<1, 256>>>(out);
    // 8. copy z_seq and c_seq into d_out
    copyout_kernel<<<24576, 256>>>(out);
}